// round 6
// baseline (speedup 1.0000x reference)
#include <cuda_runtime.h>
#include <math.h>

#define Bn 4
#define CI 128
#define CO 128
#define Hn 128
#define Wn 128
#define HW (Hn*Wn)
#define KK 9
#define PIX 32
#define CIP (CI + 4)     // padded row for conflict-free STS.128

// packed fp32x2 helpers (Blackwell sm_103a)
#define PACKF2(d, a, b) asm("mov.b64 %0, {%1, %2};" : "=l"(d) : "f"(a), "f"(b))
#define FMAF2(d, a, b, c) asm("fma.rn.f32x2 %0, %1, %2, %3;" : "=l"(d) : "l"(a), "l"(b), "l"(c))
union F2U { unsigned long long u; float2 f; };

// ---------------- scratch (static device allocations, allowed) ----------------
__device__ __align__(16) float g_xT[Bn*HW*CI];       // x in NHWC          33.5 MB
__device__ __align__(16) float g_offp[2][Bn*18*HW];  // partial offset conv  9.4 MB
__device__ __align__(16) float g_wT[KK*CI*CO];       // w_dcn [k][c4][o][4] 0.6 MB
__device__ __align__(16) float g_conv[Bn*CO*HW];     // pre-BN output      33.5 MB
__device__ float g_scale[CO];
__device__ float g_shift[CO];

// ---------------- K1: NCHW -> NHWC transpose of x ----------------
__global__ void k_transpose_x(const float* __restrict__ in) {
    __shared__ float t[32][33];
    int wb = blockIdx.x * 32, cb = blockIdx.y * 32;
    int by = blockIdx.z;                 // b*Hn + y
    int b = by >> 7, y = by & 127;
    t[threadIdx.y][threadIdx.x] =
        in[((b*CI + cb + threadIdx.y)*Hn + y)*Wn + wb + threadIdx.x];
    __syncthreads();
    g_xT[(by*Wn + wb + threadIdx.y)*CI + cb + threadIdx.x] = t[threadIdx.x][threadIdx.y];
}

// ---------------- K2: w_dcn [o][c][k] -> [k][c>>2][o][c&3] ----------------
__global__ void k_transpose_w(const float* __restrict__ w) {
    int i = blockIdx.x * blockDim.x + threadIdx.x;
    if (i >= CO*CI*KK) return;
    int o = i / (CI*KK);
    int r = i % (CI*KK);
    int c = r / KK;
    int kk = r % KK;
    g_wT[((kk*(CI/4) + (c >> 2))*CO + o)*4 + (c & 3)] = w[i];
}

// ---------------- K3: offset conv (18 out ch, 3x3, pad 1), CI split over z ----------------
__global__ __launch_bounds__(128) void k_offset_conv(
    const float* __restrict__ x, const float* __restrict__ w_off,
    const float* __restrict__ b_off) {
    __shared__ __align__(16) float sw[64*9*18];      // 41.5 KB chunk of weights
    int h = blockIdx.x, b = blockIdx.y, z = blockIdx.z;
    int c0 = z * 64;
    int w = threadIdx.x;

    unsigned long long acc2[9];
#pragma unroll
    for (int j = 0; j < 9; j++) acc2[j] = 0ull;      // == (0.0f, 0.0f)

    for (int e = threadIdx.x; e < 64*9*18; e += 128) {
        int cl = e / 162, r = e % 162, t = r / 18, j = r % 18;
        sw[e] = w_off[((j*CI + c0 + cl)*3 + t/3)*3 + t%3];
    }
    __syncthreads();
    for (int cl = 0; cl < 64; cl++) {
        const float* xp = x + (size_t)(b*CI + c0 + cl)*HW;
#pragma unroll
        for (int t = 0; t < 9; t++) {
            int yy = h + t/3 - 1;
            int xx = w + t%3 - 1;
            float xv = (yy >= 0 && yy < Hn && xx >= 0 && xx < Wn)
                     ? xp[yy*Wn + xx] : 0.f;
            unsigned long long xv2;
            PACKF2(xv2, xv, xv);
            const unsigned long long* swp =
                (const unsigned long long*)&sw[(cl*9 + t)*18];
#pragma unroll
            for (int j = 0; j < 9; j++) FMAF2(acc2[j], xv2, swp[j], acc2[j]);
        }
    }
#pragma unroll
    for (int jj = 0; jj < 9; jj++) {
        F2U u; u.u = acc2[jj];
        float b0 = (z == 0) ? b_off[2*jj]     : 0.f;
        float b1 = (z == 0) ? b_off[2*jj + 1] : 0.f;
        g_offp[z][((b*18 + 2*jj    )*Hn + h)*Wn + w] = u.f.x + b0;
        g_offp[z][((b*18 + 2*jj + 1)*Hn + h)*Wn + w] = u.f.y + b1;
    }
}

// ---------------- K4: fused deformable sampling + GEMM ----------------
// grid (Wn/PIX, Hn, Bn); 256 threads; thread = 2 out-ch (og, og+64) x 8 pixels.
// f32x2 along channel pairs; acc = 16 u64 = 32 regs -> 50% occupancy target.
__global__ __launch_bounds__(256, 4) void k_main() {
    const int w0  = blockIdx.x * PIX;
    const int h   = blockIdx.y;
    const int b   = blockIdx.z;
    const int tid = threadIdx.x;
    const int og  = tid & 63;
    const int pg  = tid >> 6;            // 0..3, 8 pixels each

    __shared__ __align__(16) float sS[PIX][CIP];     // sampled[pix][c]  16.9 KB
    __shared__ int   sIdx[KK][4][PIX];               // 4.6 KB
    __shared__ float sWt[KK][4][PIX];                // 4.6 KB

    // --- precompute corner indices/weights for ALL 9 taps ---
    for (int it = tid; it < KK*PIX; it += 256) {
        int k = it >> 5, pix = it & 31;
        int w = w0 + pix;
        int oidx = ((b*18 + 2*k)*Hn + h)*Wn + w;
        float dy = g_offp[0][oidx]      + g_offp[1][oidx];
        float dx = g_offp[0][oidx + HW] + g_offp[1][oidx + HW];
        float ys = (float)(h - 1 + (k / 3)) + dy;
        float xs = (float)(w - 1 + (k % 3)) + dx;
        float y0f = floorf(ys), x0f = floorf(xs);
        float wy = ys - y0f, wx = xs - x0f;
        int y0 = (int)y0f, x0 = (int)x0f;
        int y1 = y0 + 1, x1 = x0 + 1;
        float vy0 = (y0 >= 0 && y0 < Hn) ? 1.f : 0.f;
        float vy1 = (y1 >= 0 && y1 < Hn) ? 1.f : 0.f;
        float vx0 = (x0 >= 0 && x0 < Wn) ? 1.f : 0.f;
        float vx1 = (x1 >= 0 && x1 < Wn) ? 1.f : 0.f;
        int y0c = min(max(y0, 0), Hn-1), y1c = min(max(y1, 0), Hn-1);
        int x0c = min(max(x0, 0), Wn-1), x1c = min(max(x1, 0), Wn-1);
        int base = b * HW;
        sIdx[k][0][pix] = (base + y0c*Wn + x0c)*CI;
        sIdx[k][1][pix] = (base + y0c*Wn + x1c)*CI;
        sIdx[k][2][pix] = (base + y1c*Wn + x0c)*CI;
        sIdx[k][3][pix] = (base + y1c*Wn + x1c)*CI;
        sWt[k][0][pix] = (1.f - wy)*(1.f - wx)*vy0*vx0;
        sWt[k][1][pix] = (1.f - wy)*wx       *vy0*vx1;
        sWt[k][2][pix] = wy       *(1.f - wx)*vy1*vx0;
        sWt[k][3][pix] = wy       *wx        *vy1*vx1;
    }
    __syncthreads();

    unsigned long long acc0[8], acc1[8];
#pragma unroll
    for (int p = 0; p < 8; p++) { acc0[p] = 0ull; acc1[p] = 0ull; }

    const int spix = tid >> 3;           // sampler: pixel 0..31
    const int sc   = (tid & 7) * 4;      // sampler: channel quad base

    for (int k = 0; k < KK; k++) {
        // --- sampling: 256 threads, 4 iters over channel blocks ---
        {
            int i0 = sIdx[k][0][spix], i1 = sIdx[k][1][spix];
            int i2 = sIdx[k][2][spix], i3 = sIdx[k][3][spix];
            float w00 = sWt[k][0][spix], w01 = sWt[k][1][spix];
            float w10 = sWt[k][2][spix], w11 = sWt[k][3][spix];
#pragma unroll
            for (int cc = 0; cc < CI; cc += 32) {
                int c = cc + sc;
                float4 p0 = *(const float4*)(g_xT + i0 + c);
                float4 p1 = *(const float4*)(g_xT + i1 + c);
                float4 p2 = *(const float4*)(g_xT + i2 + c);
                float4 p3 = *(const float4*)(g_xT + i3 + c);
                float4 v;
                v.x = w00*p0.x + w01*p1.x + w10*p2.x + w11*p3.x;
                v.y = w00*p0.y + w01*p1.y + w10*p2.y + w11*p3.y;
                v.z = w00*p0.z + w01*p1.z + w10*p2.z + w11*p3.z;
                v.w = w00*p0.w + w01*p1.w + w10*p2.w + w11*p3.w;
                *(float4*)(&sS[spix][c]) = v;
            }
        }
        __syncthreads();

        // --- GEMM: 2 out-ch x 8 pixels, f32x2 over channel pairs ---
        // per c4: 2 LDG.128 (weights) + 8 broadcast LDS.128 (samples) + 32 FMA2
        const float* wk = g_wT + k*(CI/4)*CO*4;
        const float* srow = &sS[pg*8][0];
#pragma unroll 1
        for (int c4 = 0; c4 < CI/4; c4++) {
            const float* wbase = wk + (c4*CO + og)*4;
            ulonglong2 q0 = *(const ulonglong2*)(wbase);
            ulonglong2 q1 = *(const ulonglong2*)(wbase + 64*4);
            const float* sp = srow + c4*4;
#pragma unroll
            for (int p = 0; p < 8; p++) {
                ulonglong2 s = *(const ulonglong2*)(sp + p*CIP);
                FMAF2(acc0[p], q0.x, s.x, acc0[p]);
                FMAF2(acc0[p], q0.y, s.y, acc0[p]);
                FMAF2(acc1[p], q1.x, s.x, acc1[p]);
                FMAF2(acc1[p], q1.y, s.y, acc1[p]);
            }
        }
        __syncthreads();
    }

    // horizontal add (even+odd channel partials) and write out
    float v0[8], v1[8];
#pragma unroll
    for (int p = 0; p < 8; p++) {
        F2U u;
        u.u = acc0[p]; v0[p] = u.f.x + u.f.y;
        u.u = acc1[p]; v1[p] = u.f.x + u.f.y;
    }
    size_t pbase = (size_t)(b*CO)*HW + h*Wn + w0 + pg*8;
    float* d0 = g_conv + pbase + (size_t)(og      )*HW;
    float* d1 = g_conv + pbase + (size_t)(og + 64 )*HW;
    *(float4*)(d0)     = make_float4(v0[0], v0[1], v0[2], v0[3]);
    *(float4*)(d0 + 4) = make_float4(v0[4], v0[5], v0[6], v0[7]);
    *(float4*)(d1)     = make_float4(v1[0], v1[1], v1[2], v1[3]);
    *(float4*)(d1 + 4) = make_float4(v1[4], v1[5], v1[6], v1[7]);
}

// ---------------- K5: BN stats per channel ----------------
__global__ void k_bn_stats(const float* __restrict__ gamma,
                           const float* __restrict__ beta) {
    int o = blockIdx.x, tid = threadIdx.x;   // 256 threads
    float s = 0.f, s2 = 0.f;
    for (int b = 0; b < Bn; b++) {
        const float* p = g_conv + (size_t)(b*CO + o)*HW;
        for (int i = tid; i < HW; i += 256) {
            float v = p[i];
            s += v;
            s2 = fmaf(v, v, s2);
        }
    }
    __shared__ float rs[8], rs2[8];
#pragma unroll
    for (int off = 16; off; off >>= 1) {
        s  += __shfl_down_sync(0xffffffffu, s,  off);
        s2 += __shfl_down_sync(0xffffffffu, s2, off);
    }
    if ((tid & 31) == 0) { rs[tid >> 5] = s; rs2[tid >> 5] = s2; }
    __syncthreads();
    if (tid < 32) {
        s  = (tid < 8) ? rs[tid]  : 0.f;
        s2 = (tid < 8) ? rs2[tid] : 0.f;
#pragma unroll
        for (int off = 4; off; off >>= 1) {
            s  += __shfl_down_sync(0xffffffffu, s,  off);
            s2 += __shfl_down_sync(0xffffffffu, s2, off);
        }
        if (tid == 0) {
            float inv_n = 1.f / (float)(Bn*HW);
            float mean = s * inv_n;
            float var  = s2 * inv_n - mean*mean;
            float r = 1.f / sqrtf(var + 0.001f);
            float sc = gamma[o] * r;
            g_scale[o] = sc;
            g_shift[o] = beta[o] - mean*sc;
        }
    }
}

// ---------------- K6: apply BN + ReLU ----------------
__global__ void k_bn_apply(float* __restrict__ out) {
    int i = blockIdx.x * blockDim.x + threadIdx.x;   // float4 index
    int ch = (i >> 12) & 127;                        // plane = 16384 elems = 4096 float4
    float4 v = ((const float4*)g_conv)[i];
    float sc = g_scale[ch], sh = g_shift[ch];
    v.x = fmaxf(fmaf(v.x, sc, sh), 0.f);
    v.y = fmaxf(fmaf(v.y, sc, sh), 0.f);
    v.z = fmaxf(fmaf(v.z, sc, sh), 0.f);
    v.w = fmaxf(fmaf(v.w, sc, sh), 0.f);
    ((float4*)out)[i] = v;
}

// ---------------- launch ----------------
extern "C" void kernel_launch(void* const* d_in, const int* in_sizes, int n_in,
                              void* d_out, int out_size) {
    const float* x     = (const float*)d_in[0];
    const float* w_off = (const float*)d_in[1];
    const float* b_off = (const float*)d_in[2];
    const float* w_dcn = (const float*)d_in[3];
    const float* gamma = (const float*)d_in[4];
    const float* beta  = (const float*)d_in[5];
    float* out = (float*)d_out;

    k_transpose_x<<<dim3(Wn/32, CI/32, Bn*Hn), dim3(32, 32)>>>(x);
    k_transpose_w<<<(CO*CI*KK + 255)/256, 256>>>(w_dcn);
    k_offset_conv<<<dim3(Hn, Bn, 2), 128>>>(x, w_off, b_off);
    k_main<<<dim3(Wn/PIX, Hn, Bn), 256>>>();
    k_bn_stats<<<CO, 256>>>(gamma, beta);
    k_bn_apply<<<(Bn*CO*HW/4)/256, 256>>>(out);
}

// round 8
// speedup vs baseline: 2.0958x; 2.0958x over previous
#include <cuda_runtime.h>
#include <math.h>
#include <cstdint>

#define Bn 4
#define CI 128
#define CO 128
#define Hn 128
#define Wn 128
#define HW (Hn*Wn)
#define KK 9
#define CIP 132          // padded pixel-row stride in floats

// packed fp32x2 helpers (for offset conv)
#define PACKF2(d, a, b) asm("mov.b64 %0, {%1, %2};" : "=l"(d) : "f"(a), "f"(b))
#define FMAF2(d, a, b, c) asm("fma.rn.f32x2 %0, %1, %2, %3;" : "=l"(d) : "l"(a), "l"(b), "l"(c))
union F2U { unsigned long long u; float2 f; };

// tf32 convert (round to nearest)
#define CVT_TF32(u, f) asm("cvt.rna.tf32.f32 %0, %1;" : "=r"(u) : "f"(f))

// warp-level tensor core MMA: D(16x8) += A(16x8,tf32) * B(8x8,tf32)
__device__ __forceinline__ void mma_tf32(float* c, const uint4& a, uint32_t b0, uint32_t b1) {
    asm volatile("mma.sync.aligned.m16n8k8.row.col.f32.tf32.tf32.f32 "
        "{%0,%1,%2,%3}, {%4,%5,%6,%7}, {%8,%9}, {%0,%1,%2,%3};"
        : "+f"(c[0]), "+f"(c[1]), "+f"(c[2]), "+f"(c[3])
        : "r"(a.x), "r"(a.y), "r"(a.z), "r"(a.w), "r"(b0), "r"(b1));
}

// ---------------- scratch ----------------
__device__ __align__(16) float g_xT[Bn*HW*CI];       // x in NHWC
__device__ __align__(16) float g_offp[2][Bn*18*HW];  // partial offset conv
__device__ __align__(16) float g_wF[KK*16*8*32*4];   // weights in A-fragment order (tf32)
__device__ __align__(16) float g_conv[Bn*CO*HW];     // pre-BN output
__device__ float g_scale[CO];
__device__ float g_shift[CO];

// ---------------- K1: NCHW -> NHWC transpose of x ----------------
__global__ void k_transpose_x(const float* __restrict__ in) {
    __shared__ float t[32][33];
    int wb = blockIdx.x * 32, cb = blockIdx.y * 32;
    int by = blockIdx.z;
    int b = by >> 7, y = by & 127;
    t[threadIdx.y][threadIdx.x] =
        in[((b*CI + cb + threadIdx.y)*Hn + y)*Wn + wb + threadIdx.x];
    __syncthreads();
    g_xT[(by*Wn + wb + threadIdx.y)*CI + cb + threadIdx.x] = t[threadIdx.x][threadIdx.y];
}

// ---------------- K2: w_dcn -> A-fragment prepack (tf32) ----------------
// A = weights, M=o(128), K=c. Fragment m16n8k8: lane l holds
// a0=(o=ost*16+l/4,       c=s*8+l%4), a1=(o+8, c), a2=(o, c+4), a3=(o+8, c+4).
// g_wF[tap][step s][ostripe][lane][4]
__global__ void k_prep_w(const float* __restrict__ w) {
    int i = blockIdx.x * blockDim.x + threadIdx.x;
    if (i >= KK*16*8*32) return;
    int l = i & 31;
    int r = i >> 5;
    int ost = r & 7;  r >>= 3;
    int s = r & 15;
    int tap = r >> 4;
    int o = ost*16 + (l >> 2);
    int c = s*8 + (l & 3);
    // w_dcn shape (CO, CI, 3, 3): index o*CI*9 + c*9 + tap
    float a0 = w[(o*CI + c)*9 + tap];
    float a1 = w[((o+8)*CI + c)*9 + tap];
    float a2 = w[(o*CI + c + 4)*9 + tap];
    float a3 = w[((o+8)*CI + c + 4)*9 + tap];
    uint4 u;
    CVT_TF32(u.x, a0); CVT_TF32(u.y, a1); CVT_TF32(u.z, a2); CVT_TF32(u.w, a3);
    ((uint4*)g_wF)[i] = u;
}

// ---------------- K3: offset conv (18 out ch, 3x3, pad 1), CI split over z ----------------
__global__ __launch_bounds__(128) void k_offset_conv(
    const float* __restrict__ x, const float* __restrict__ w_off,
    const float* __restrict__ b_off) {
    __shared__ __align__(16) float sw[64*9*18];
    int h = blockIdx.x, b = blockIdx.y, z = blockIdx.z;
    int c0 = z * 64;
    int w = threadIdx.x;

    unsigned long long acc2[9];
#pragma unroll
    for (int j = 0; j < 9; j++) acc2[j] = 0ull;

    for (int e = threadIdx.x; e < 64*9*18; e += 128) {
        int cl = e / 162, r = e % 162, t = r / 18, j = r % 18;
        sw[e] = w_off[((j*CI + c0 + cl)*3 + t/3)*3 + t%3];
    }
    __syncthreads();
    for (int cl = 0; cl < 64; cl++) {
        const float* xp = x + (size_t)(b*CI + c0 + cl)*HW;
#pragma unroll
        for (int t = 0; t < 9; t++) {
            int yy = h + t/3 - 1;
            int xx = w + t%3 - 1;
            float xv = (yy >= 0 && yy < Hn && xx >= 0 && xx < Wn)
                     ? xp[yy*Wn + xx] : 0.f;
            unsigned long long xv2;
            PACKF2(xv2, xv, xv);
            const unsigned long long* swp =
                (const unsigned long long*)&sw[(cl*9 + t)*18];
#pragma unroll
            for (int j = 0; j < 9; j++) FMAF2(acc2[j], xv2, swp[j], acc2[j]);
        }
    }
#pragma unroll
    for (int jj = 0; jj < 9; jj++) {
        F2U u; u.u = acc2[jj];
        float b0 = (z == 0) ? b_off[2*jj]     : 0.f;
        float b1 = (z == 0) ? b_off[2*jj + 1] : 0.f;
        g_offp[z][((b*18 + 2*jj    )*Hn + h)*Wn + w] = u.f.x + b0;
        g_offp[z][((b*18 + 2*jj + 1)*Hn + h)*Wn + w] = u.f.y + b1;
    }
}

// ---------------- K4: deformable sampling + mma.sync TF32 GEMM ----------------
// block = (h, b): 128 pixels x 128 out channels. 256 threads = 8 warps.
// warp grid: wm = wid>>1 (4 M-warps, 32 o each), wc = wid&1 (2 N-warps, 64 pix each).
#define OFF_IDX 0                         // int   [9][4][128] 18432 B
#define OFF_WT  18432                     // float [9][4][128] 18432 B
#define OFF_S   36864                     // float [128][CIP]  67584 B
#define SMEM_TOT (OFF_S + 128*CIP*4)

__global__ __launch_bounds__(256, 2) void k_main() {
    extern __shared__ __align__(16) char smem[];
    const int h   = blockIdx.x;
    const int b   = blockIdx.y;
    const int tid = threadIdx.x;
    const int wid = tid >> 5;
    const int l   = tid & 31;
    const int wm  = wid >> 1;
    const int wc  = wid & 1;

    int*   sIdx = (int*)(smem + OFF_IDX);     // [k][4][128]
    float* sWt  = (float*)(smem + OFF_WT);    // [k][4][128]
    float* sS   = (float*)(smem + OFF_S);     // [pix][CIP], tf32 values

    // --- precompute corner indices/weights for all 9 taps x 128 pixels ---
    for (int it = tid; it < KK*128; it += 256) {
        int k = it >> 7, pix = it & 127;
        int w = pix;
        int oidx = ((b*18 + 2*k)*Hn + h)*Wn + w;
        float dy = g_offp[0][oidx]      + g_offp[1][oidx];
        float dx = g_offp[0][oidx + HW] + g_offp[1][oidx + HW];
        float ys = (float)(h - 1 + (k / 3)) + dy;
        float xs = (float)(w - 1 + (k % 3)) + dx;
        float y0f = floorf(ys), x0f = floorf(xs);
        float wy = ys - y0f, wx = xs - x0f;
        int y0 = (int)y0f, x0 = (int)x0f;
        int y1 = y0 + 1, x1 = x0 + 1;
        float vy0 = (y0 >= 0 && y0 < Hn) ? 1.f : 0.f;
        float vy1 = (y1 >= 0 && y1 < Hn) ? 1.f : 0.f;
        float vx0 = (x0 >= 0 && x0 < Wn) ? 1.f : 0.f;
        float vx1 = (x1 >= 0 && x1 < Wn) ? 1.f : 0.f;
        int y0c = min(max(y0, 0), Hn-1), y1c = min(max(y1, 0), Hn-1);
        int x0c = min(max(x0, 0), Wn-1), x1c = min(max(x1, 0), Wn-1);
        int base = b * HW;
        int* ip = sIdx + (k*4)*128;
        float* wp = sWt + (k*4)*128;
        ip[0*128 + pix] = (base + y0c*Wn + x0c)*CI;
        ip[1*128 + pix] = (base + y0c*Wn + x1c)*CI;
        ip[2*128 + pix] = (base + y1c*Wn + x0c)*CI;
        ip[3*128 + pix] = (base + y1c*Wn + x1c)*CI;
        wp[0*128 + pix] = (1.f - wy)*(1.f - wx)*vy0*vx0;
        wp[1*128 + pix] = (1.f - wy)*wx       *vy0*vx1;
        wp[2*128 + pix] = wy       *(1.f - wx)*vy1*vx0;
        wp[3*128 + pix] = wy       *wx        *vy1*vx1;
    }

    float acc[2][8][4];
#pragma unroll
    for (int st = 0; st < 2; st++)
#pragma unroll
        for (int t = 0; t < 8; t++)
#pragma unroll
            for (int j = 0; j < 4; j++) acc[st][t][j] = 0.f;

    const int spix = tid >> 3;            // sampler: pixel 0..31 (per pass)
    const int sc   = (tid & 7) * 4;       // sampler: channel quad base

    // B lane base: pix = wc*64 + l/4 (+ t*8), c = s*8 + l%4 (+4)
    const uint32_t* bLane = (const uint32_t*)(sS + (wc*64 + (l >> 2))*CIP + (l & 3));

    for (int k = 0; k < KK; k++) {
        __syncthreads();    // protect sS from previous tap's readers
        // --- sample tap k into sS (tf32-converted) ---
        const int* ip = sIdx + (k*4)*128;
        const float* wp = sWt + (k*4)*128;
#pragma unroll
        for (int pass = 0; pass < 4; pass++) {
            int pix = pass*32 + spix;
            int i0 = ip[0*128 + pix], i1 = ip[1*128 + pix];
            int i2 = ip[2*128 + pix], i3 = ip[3*128 + pix];
            float w00 = wp[0*128 + pix], w01 = wp[1*128 + pix];
            float w10 = wp[2*128 + pix], w11 = wp[3*128 + pix];
#pragma unroll
            for (int cc = 0; cc < CI; cc += 32) {
                int c = cc + sc;
                float4 p0 = *(const float4*)(g_xT + i0 + c);
                float4 p1 = *(const float4*)(g_xT + i1 + c);
                float4 p2 = *(const float4*)(g_xT + i2 + c);
                float4 p3 = *(const float4*)(g_xT + i3 + c);
                float4 v;
                v.x = w00*p0.x + w01*p1.x + w10*p2.x + w11*p3.x;
                v.y = w00*p0.y + w01*p1.y + w10*p2.y + w11*p3.y;
                v.z = w00*p0.z + w01*p1.z + w10*p2.z + w11*p3.z;
                v.w = w00*p0.w + w01*p1.w + w10*p2.w + w11*p3.w;
                uint4 u;
                CVT_TF32(u.x, v.x); CVT_TF32(u.y, v.y);
                CVT_TF32(u.z, v.z); CVT_TF32(u.w, v.w);
                *(uint4*)(sS + pix*CIP + c) = u;
            }
        }
        __syncthreads();

        // --- GEMM: 16 K=8 steps; per step 2 A-frag LDG.128 + 8 B tiles ---
        const uint4* aBase = (const uint4*)g_wF + ((k*16)*8 + 2*wm)*32 + l;
#pragma unroll 2
        for (int s = 0; s < 16; s++) {
            uint4 aF0 = aBase[s*256];          // ostripe 2*wm
            uint4 aF1 = aBase[s*256 + 32];     // ostripe 2*wm + 1
            const uint32_t* bp = bLane + s*8;
#pragma unroll
            for (int t = 0; t < 8; t++) {
                uint32_t b0 = bp[t*8*CIP];
                uint32_t b1 = bp[t*8*CIP + 4];
                mma_tf32(acc[0][t], aF0, b0, b1);
                mma_tf32(acc[1][t], aF1, b0, b1);
            }
        }
    }

    // --- epilogue: D[o][pix] fragments -> g_conv (NCHW) ---
#pragma unroll
    for (int st = 0; st < 2; st++) {
        int o = 32*wm + st*16 + (l >> 2);
#pragma unroll
        for (int t = 0; t < 8; t++) {
            int px = wc*64 + t*8 + 2*(l & 3);
            float* d = g_conv + ((size_t)(b*CO + o)*Hn + h)*Wn + px;
            *(float2*)d            = make_float2(acc[st][t][0], acc[st][t][1]);
            *(float2*)(d + 8*HW)   = make_float2(acc[st][t][2], acc[st][t][3]);
        }
    }
}

// ---------------- K5: BN stats per channel ----------------
__global__ void k_bn_stats(const float* __restrict__ gamma,
                           const float* __restrict__ beta) {
    int o = blockIdx.x, tid = threadIdx.x;
    float s = 0.f, s2 = 0.f;
    for (int b = 0; b < Bn; b++) {
        const float* p = g_conv + (size_t)(b*CO + o)*HW;
        for (int i = tid; i < HW; i += 256) {
            float v = p[i];
            s += v;
            s2 = fmaf(v, v, s2);
        }
    }
    __shared__ float rs[8], rs2[8];
#pragma unroll
    for (int off = 16; off; off >>= 1) {
        s  += __shfl_down_sync(0xffffffffu, s,  off);
        s2 += __shfl_down_sync(0xffffffffu, s2, off);
    }
    if ((tid & 31) == 0) { rs[tid >> 5] = s; rs2[tid >> 5] = s2; }
    __syncthreads();
    if (tid < 32) {
        s  = (tid < 8) ? rs[tid]  : 0.f;
        s2 = (tid < 8) ? rs2[tid] : 0.f;
#pragma unroll
        for (int off = 4; off; off >>= 1) {
            s  += __shfl_down_sync(0xffffffffu, s,  off);
            s2 += __shfl_down_sync(0xffffffffu, s2, off);
        }
        if (tid == 0) {
            float inv_n = 1.f / (float)(Bn*HW);
            float mean = s * inv_n;
            float var  = s2 * inv_n - mean*mean;
            float r = 1.f / sqrtf(var + 0.001f);
            float sc = gamma[o] * r;
            g_scale[o] = sc;
            g_shift[o] = beta[o] - mean*sc;
        }
    }
}

// ---------------- K6: apply BN + ReLU ----------------
__global__ void k_bn_apply(float* __restrict__ out) {
    int i = blockIdx.x * blockDim.x + threadIdx.x;
    int ch = (i >> 12) & 127;
    float4 v = ((const float4*)g_conv)[i];
    float sc = g_scale[ch], sh = g_shift[ch];
    v.x = fmaxf(fmaf(v.x, sc, sh), 0.f);
    v.y = fmaxf(fmaf(v.y, sc, sh), 0.f);
    v.z = fmaxf(fmaf(v.z, sc, sh), 0.f);
    v.w = fmaxf(fmaf(v.w, sc, sh), 0.f);
    ((float4*)out)[i] = v;
}

// ---------------- launch ----------------
extern "C" void kernel_launch(void* const* d_in, const int* in_sizes, int n_in,
                              void* d_out, int out_size) {
    const float* x     = (const float*)d_in[0];
    const float* w_off = (const float*)d_in[1];
    const float* b_off = (const float*)d_in[2];
    const float* w_dcn = (const float*)d_in[3];
    const float* gamma = (const float*)d_in[4];
    const float* beta  = (const float*)d_in[5];
    float* out = (float*)d_out;

    cudaFuncSetAttribute(k_main, cudaFuncAttributeMaxDynamicSharedMemorySize, SMEM_TOT);

    k_transpose_x<<<dim3(Wn/32, CI/32, Bn*Hn), dim3(32, 32)>>>(x);
    k_prep_w<<<(KK*16*8*32 + 255)/256, 256>>>(w_dcn);
    k_offset_conv<<<dim3(Hn, Bn, 2), 128>>>(x, w_off, b_off);
    k_main<<<dim3(Hn, Bn), 256, SMEM_TOT>>>();
    k_bn_stats<<<CO, 256>>>(gamma, beta);
    k_bn_apply<<<(Bn*CO*HW/4)/256, 256>>>(out);
}